// round 4
// baseline (speedup 1.0000x reference)
#include <cuda_runtime.h>

// Problem dims (fixed by reference)
#define T0_R 8192
#define T0_C 4096
#define T1_R 4096
#define T1_C 2048
#define NG   1024
#define NMAP 512
#define CAP  128     // max rows per group; Binomial(8192,1/1024) tail beyond 128 ~ 0

// -------- device scratch (allocation-free) --------
__device__ float  d_p2[T0_C];        // column sums of exp(theta0)
__device__ float  d_p1[T1_R];        // row sums of exp(theta1)
__device__ int    d_cnt[NG];
__device__ int    d_lst[NG * CAP];
__device__ double d_loss[2];         // [0]=sum sq for loss_a, [1]=sum sq for loss_b

// -------- block reduction (sum), result valid on thread 0 --------
__device__ __forceinline__ float block_reduce_sum(float v) {
    __shared__ float s[32];
    int lane = threadIdx.x & 31;
    int wid  = threadIdx.x >> 5;
    #pragma unroll
    for (int o = 16; o > 0; o >>= 1) v += __shfl_down_sync(0xffffffffu, v, o);
    if (lane == 0) s[wid] = v;
    __syncthreads();
    int nw = blockDim.x >> 5;
    v = (threadIdx.x < nw) ? s[threadIdx.x] : 0.0f;
    if (wid == 0) {
        #pragma unroll
        for (int o = 16; o > 0; o >>= 1) v += __shfl_down_sync(0xffffffffu, v, o);
    }
    return v;
}

// -------- 1) zero scratch --------
__global__ void k_zero() {
    int t = blockIdx.x * blockDim.x + threadIdx.x;
    int stride = gridDim.x * blockDim.x;
    for (int i = t; i < T0_C; i += stride) d_p2[i] = 0.0f;
    for (int i = t; i < NG;   i += stride) d_cnt[i] = 0;
    if (t < 2) d_loss[t] = 0.0;
}

// -------- 2) build per-group row lists (idx0 is int32 — JAX x64 disabled) ----
__global__ void k_build(const int* __restrict__ idx0, int n_idx) {
    int i = blockIdx.x * blockDim.x + threadIdx.x;
    if (i < T0_R && i < n_idx) {
        int g = idx0[i];
        if (g < 0) g = 0;
        if (g >= NG) g = NG - 1;           // defensive clamp: no OOB ever
        int slot = atomicAdd(&d_cnt[g], 1);
        if (slot < CAP) d_lst[g * CAP + slot] = i;
    }
}

// -------- 3) obs A: per-group segment sum of exp(theta0) fused with loss_a and p2 --------
// grid = NG blocks, 256 threads; each thread owns 16 columns.
__global__ void __launch_bounds__(256) k_obsA(const float* __restrict__ theta0,
                                              const float* __restrict__ obs0) {
    int g = blockIdx.x;
    int cnt = d_cnt[g];
    if (cnt > CAP) cnt = CAP;
    const int* rows = &d_lst[g * CAP];

    float acc[16];
    #pragma unroll
    for (int i = 0; i < 16; i++) acc[i] = 0.0f;

    for (int j = 0; j < cnt; j++) {
        int r = rows[j];
        if (r < 0 || r >= T0_R) continue;   // defensive
        const float* tr = theta0 + (size_t)r * T0_C;
        #pragma unroll
        for (int i = 0; i < 16; i++) {
            acc[i] += __expf(tr[threadIdx.x + i * 256]);
        }
    }

    const float* orow = obs0 + (size_t)g * T0_C;
    float local = 0.0f;
    #pragma unroll
    for (int i = 0; i < 16; i++) {
        int c = threadIdx.x + i * 256;
        atomicAdd(&d_p2[c], acc[i]);
        float diff = orow[c] - acc[i];
        local += diff * diff;
    }
    float tot = block_reduce_sum(local);
    if (threadIdx.x == 0) atomicAdd(&d_loss[0], (double)tot);
}

// -------- 4) p1 = rowsum of exp(theta1). grid = T1_R blocks, 256 threads --------
__global__ void __launch_bounds__(256) k_p1(const float* __restrict__ theta1) {
    int r = blockIdx.x;
    const float* tr = theta1 + (size_t)r * T1_C;
    float local = 0.0f;
    #pragma unroll
    for (int i = 0; i < T1_C / 256; i++) {
        local += __expf(tr[threadIdx.x + i * 256]);
    }
    float tot = block_reduce_sum(local);
    if (threadIdx.x == 0) d_p1[r] = tot;
}

// -------- 5) m1 = mapping1 @ p1, fused with loss_b. grid = NMAP blocks --------
__global__ void __launch_bounds__(256) k_obsB(const float* __restrict__ mapping1,
                                              const float* __restrict__ obs1) {
    int o = blockIdx.x;
    const float* mrow = mapping1 + (size_t)o * T1_R;
    float local = 0.0f;
    #pragma unroll
    for (int i = 0; i < T1_R / 256; i++) {
        int c = threadIdx.x + i * 256;
        local += mrow[c] * d_p1[c];
    }
    float tot = block_reduce_sum(local);
    if (threadIdx.x == 0) {
        float diff = obs1[o] - tot;
        atomicAdd(&d_loss[1], (double)(diff * diff));
    }
}

// -------- 6) loss_c from p2 + final combine. 1 block, 256 threads --------
__global__ void __launch_bounds__(256) k_final(const float* __restrict__ obs2,
                                               float* __restrict__ out) {
    float local = 0.0f;
    #pragma unroll
    for (int i = 0; i < T0_C / 256; i++) {
        int c = threadIdx.x + i * 256;
        float diff = obs2[c] - d_p2[c];
        local += diff * diff;
    }
    float tot = block_reduce_sum(local);
    if (threadIdx.x == 0) {
        double loss_a = d_loss[0] / ((double)NG * (double)T0_C);
        double loss_b = d_loss[1] / (double)NMAP;
        double loss_c = 0.5 * ((double)tot / (double)T0_C);
        out[0] = (float)((loss_a + loss_b + loss_c) / 3.0);
    }
}

extern "C" void kernel_launch(void* const* d_in, const int* in_sizes, int n_in,
                              void* d_out, int out_size) {
    const float* theta0   = (const float*)d_in[0];
    const float* theta1   = (const float*)d_in[1];
    const float* obs0     = (const float*)d_in[2];
    const float* obs1     = (const float*)d_in[3];
    const float* obs2     = (const float*)d_in[4];
    const int*   idx0     = (const int*)d_in[5];     // int32: JAX x64 disabled
    const float* mapping1 = (const float*)d_in[6];
    float* out = (float*)d_out;

    k_zero<<<8, 256>>>();
    k_build<<<(T0_R + 255) / 256, 256>>>(idx0, in_sizes[5]);
    k_obsA<<<NG, 256>>>(theta0, obs0);
    k_p1<<<T1_R, 256>>>(theta1);
    k_obsB<<<NMAP, 256>>>(mapping1, obs1);
    k_final<<<1, 256>>>(obs2, out);
}